// round 16
// baseline (speedup 1.0000x reference)
#include <cuda_runtime.h>
#include <cuda_bf16.h>

#define FULLMASK 0xffffffffu
#define TT 4096

// ---- device scratch (allocation-free) ----
__device__ float g_p0[64][64];    // per-block feature col sum[32] + sumsq[32]
__device__ float g_p1[16][16];    // per-block h1 sum[8] + sumsq[8]
__device__ float g_p2[16][16];    // per-block h2 sum[8] + sumsq[8]
__device__ float g_h1[2048 * 8];
__device__ float g_h2[2048 * 8];

// ============ K1: bn0 column partial stats (64 x 256; 32 rows/block) ============
__global__ __launch_bounds__(256) void k_stats0(const float* __restrict__ features) {
    __shared__ float red[8][64];
    const int tid = threadIdx.x, warp = tid >> 5, lane = tid & 31;
    const float4* fp = (const float4*)(features + (size_t)blockIdx.x * 32 * 32);
    float4 v = __ldg(fp + tid);          // columns (tid%8)*4 .. +3
    float s0 = v.x, s1 = v.y, s2 = v.z, s3 = v.w;
    float q0 = v.x * v.x, q1 = v.y * v.y, q2 = v.z * v.z, q3 = v.w * v.w;
    #pragma unroll
    for (int d = 8; d <= 16; d <<= 1) {
        s0 += __shfl_xor_sync(FULLMASK, s0, d); s1 += __shfl_xor_sync(FULLMASK, s1, d);
        s2 += __shfl_xor_sync(FULLMASK, s2, d); s3 += __shfl_xor_sync(FULLMASK, s3, d);
        q0 += __shfl_xor_sync(FULLMASK, q0, d); q1 += __shfl_xor_sync(FULLMASK, q1, d);
        q2 += __shfl_xor_sync(FULLMASK, q2, d); q3 += __shfl_xor_sync(FULLMASK, q3, d);
    }
    if (lane < 8) {
        const int c = lane * 4;
        red[warp][c + 0] = s0; red[warp][c + 1] = s1;
        red[warp][c + 2] = s2; red[warp][c + 3] = s3;
        red[warp][32 + c + 0] = q0; red[warp][32 + c + 1] = q1;
        red[warp][32 + c + 2] = q2; red[warp][32 + c + 3] = q3;
    }
    __syncthreads();
    if (tid < 64) {
        float a = 0.f;
        #pragma unroll
        for (int w = 0; w < 8; w++) a += red[w][tid];
        g_p0[blockIdx.x][tid] = a;
    }
}

// ============ K2: finalize bn0, h1 = bn0(f) @ W1^T + b1, p1 partials (16 x 128) ============
__global__ __launch_bounds__(128) void k_h1(const float* __restrict__ features,
                                            const float* __restrict__ bn0_g,
                                            const float* __restrict__ bn0_b,
                                            const float* __restrict__ W1,
                                            const float* __restrict__ b1) {
    __shared__ float s_f[128][33];
    __shared__ float sW1[256], sb1[8];
    __shared__ float s_sc0[32], s_sh0[32];
    __shared__ float s_p[4][16];
    const int tid = threadIdx.x, warp = tid >> 5, lane = tid & 31;

    sW1[tid] = W1[tid];
    sW1[tid + 128] = W1[tid + 128];
    if (tid < 8) sb1[tid] = b1[tid];

    const float* fb = features + ((size_t)blockIdx.x * 128 + warp * 32) * 32;
    #pragma unroll 8
    for (int i = 0; i < 32; i++) s_f[warp * 32 + i][lane] = fb[i * 32 + lane];

    if (tid < 32) {
        float ss = 0.f, qq = 0.f;
        #pragma unroll 8
        for (int b = 0; b < 64; b++) { ss += g_p0[b][tid]; qq += g_p0[b][32 + tid]; }
        const float mean = ss * (1.f / 2048.f);
        const float var  = qq * (1.f / 2048.f) - mean * mean;
        const float sc   = bn0_g[tid] * rsqrtf(var + 1e-5f);
        s_sc0[tid] = sc;
        s_sh0[tid] = bn0_b[tid] - mean * sc;
    }
    __syncthreads();

    float xn[32];
    #pragma unroll
    for (int c = 0; c < 32; c++) xn[c] = fmaf(s_f[tid][c], s_sc0[c], s_sh0[c]);
    float h[8];
    #pragma unroll
    for (int j = 0; j < 8; j++) {
        float a = sb1[j];
        #pragma unroll
        for (int c = 0; c < 32; c++) a = fmaf(sW1[j * 32 + c], xn[c], a);
        h[j] = a;
    }
    const int row = blockIdx.x * 128 + tid;
    float4* hp = (float4*)(g_h1 + row * 8);
    hp[0] = make_float4(h[0], h[1], h[2], h[3]);
    hp[1] = make_float4(h[4], h[5], h[6], h[7]);

    float sv[16];
    #pragma unroll
    for (int j = 0; j < 8; j++) { sv[j] = h[j]; sv[8 + j] = h[j] * h[j]; }
    #pragma unroll
    for (int d = 16; d; d >>= 1) {
        #pragma unroll
        for (int j = 0; j < 16; j++) sv[j] += __shfl_xor_sync(FULLMASK, sv[j], d);
    }
    if (lane < 16) s_p[warp][lane] = sv[lane];
    __syncthreads();
    if (tid < 16)
        g_p1[blockIdx.x][tid] = s_p[0][tid] + s_p[1][tid] + s_p[2][tid] + s_p[3][tid];
}

// ============ K3: finalize bn1, h2 = relu(bn1(h1)) @ W2^T + b2, p2 partials (16 x 128) ============
__global__ __launch_bounds__(128) void k_h2(const float* __restrict__ bn1_g,
                                            const float* __restrict__ bn1_b,
                                            const float* __restrict__ W2,
                                            const float* __restrict__ b2) {
    __shared__ float sW2[64], sb2[8];
    __shared__ float s_sc1[8], s_sh1[8];
    __shared__ float s_p[4][16];
    const int tid = threadIdx.x, warp = tid >> 5, lane = tid & 31;

    if (tid < 64) sW2[tid] = W2[tid];
    else if (tid < 72) sb2[tid - 64] = b2[tid - 64];
    if (tid < 8) {
        float ss = 0.f, qq = 0.f;
        #pragma unroll
        for (int b = 0; b < 16; b++) { ss += g_p1[b][tid]; qq += g_p1[b][8 + tid]; }
        const float mean = ss * (1.f / 2048.f);
        const float var  = qq * (1.f / 2048.f) - mean * mean;
        const float sc   = bn1_g[tid] * rsqrtf(var + 1e-5f);
        s_sc1[tid] = sc;
        s_sh1[tid] = bn1_b[tid] - mean * sc;
    }
    __syncthreads();

    const int row = blockIdx.x * 128 + tid;
    const float4* hp = (const float4*)(g_h1 + row * 8);
    const float4 v0 = hp[0], v1 = hp[1];
    float z[8] = {v0.x, v0.y, v0.z, v0.w, v1.x, v1.y, v1.z, v1.w};
    #pragma unroll
    for (int j = 0; j < 8; j++) z[j] = fmaxf(fmaf(z[j], s_sc1[j], s_sh1[j]), 0.f);
    float h[8];
    #pragma unroll
    for (int k = 0; k < 8; k++) {
        float a = sb2[k];
        #pragma unroll
        for (int j = 0; j < 8; j++) a = fmaf(sW2[k * 8 + j], z[j], a);
        h[k] = a;
    }
    float4* op = (float4*)(g_h2 + row * 8);
    op[0] = make_float4(h[0], h[1], h[2], h[3]);
    op[1] = make_float4(h[4], h[5], h[6], h[7]);

    float sv[16];
    #pragma unroll
    for (int j = 0; j < 8; j++) { sv[j] = h[j]; sv[8 + j] = h[j] * h[j]; }
    #pragma unroll
    for (int d = 16; d; d >>= 1) {
        #pragma unroll
        for (int j = 0; j < 16; j++) sv[j] += __shfl_xor_sync(FULLMASK, sv[j], d);
    }
    if (lane < 16) s_p[warp][lane] = sv[lane];
    __syncthreads();
    if (tid < 16)
        g_p2[blockIdx.x][tid] = s_p[0][tid] + s_p[1][tid] + s_p[2][tid] + s_p[3][tid];
}

// ============ K4: per-warp params preamble + R10 scan (256 x 256) ============
// Lanes 0-7 finalize bn2 & compute z; lanes 0-5 the sigmoid heads; shuffles
// broadcast. Then lane l scans steps [128l, 128l+128) in closed affine form
// (transform [[p,0],[r,p]] + offset (q1,q2)); 5-round shfl scan composes;
// butterfly reduce finishes.
__global__ __launch_bounds__(256) void k_scan(const float* __restrict__ X,
                                              const float* __restrict__ Fp,
                                              const float* __restrict__ bn2_g,
                                              const float* __restrict__ bn2_b,
                                              const float* __restrict__ W3,
                                              const float* __restrict__ b3,
                                              const float* __restrict__ pn,
                                              float* __restrict__ out) {
    const int warp = threadIdx.x >> 5, lane = threadIdx.x & 31;
    const int row = blockIdx.x * 8 + warp;
    const float cc = 0.16228221f * __ldg(Fp);   // sqrt(2^(1/3)-1)*F/pi

    // ---- per-warp params (no block sync) ----
    float zj = 0.f;
    if (lane < 8) {
        float ss = 0.f, qq = 0.f;
        #pragma unroll
        for (int b = 0; b < 16; b++) { ss += g_p2[b][lane]; qq += g_p2[b][8 + lane]; }
        const float mean = ss * (1.f / 2048.f);
        const float var  = qq * (1.f / 2048.f) - mean * mean;
        const float sc2  = __ldg(bn2_g + lane) * rsqrtf(var + 1e-5f);
        const float sh2  = __ldg(bn2_b + lane) - mean * sc2;
        zj = fmaxf(fmaf(g_h2[row * 8 + lane], sc2, sh2), 0.f);
    }
    float zz[8];
    #pragma unroll
    for (int k = 0; k < 8; k++) zz[k] = __shfl_sync(FULLMASK, zj, k);
    float sgj = 0.f;
    if (lane < 6) {
        float a = __ldg(b3 + lane) + __ldg(pn + lane);
        #pragma unroll
        for (int k = 0; k < 8; k++) a = fmaf(__ldg(W3 + lane * 8 + k), zz[k], a);
        sgj = __fdividef(1.f, 1.f + __expf(-a));
    }
    const float sg0 = __shfl_sync(FULLMASK, sgj, 0);
    const float sg1 = __shfl_sync(FULLMASK, sgj, 1);
    const float sg2 = __shfl_sync(FULLMASK, sgj, 2);
    const float sg3 = __shfl_sync(FULLMASK, sgj, 3);
    const float sg4 = __shfl_sync(FULLMASK, sgj, 4);
    const float sg5 = __shfl_sync(FULLMASK, sgj, 5);

    const float f_start = fmaf(4.5f,  sg0, 0.5f);
    const float f_inf   = fmaf(0.49f, sg1, 0.01f);
    const float f_decay = 2.f * sg2;
    const float f_T     = 2.f * sg3;
    const float w_off   = sg4;
    const float w_T     = fmaf(0.49f, sg5, 0.01f);

    const float df  = f_start - f_inf;
    const float lnD = fmaf(-2.30258509f, f_decay, -0.35667494f);  // ln(0.7*0.1^fd)
    const float H   = 10.f * __expf(-2.30258509f * f_T);          // 10*0.1^fT
    const float kf  = __fdividef(lnD, 4096.f * H);
    const float G   = __expf(kf);
    const float z0  = __fdividef(w_off, w_T);
    const float lw  = -__fdividef(1.f, 4096.f * w_T);
    const float R   = __expf(lw);

    // ---- scan (R10 body) ----
    const float* xrow = X + (size_t)row * TT;
    const int t0 = lane << 7;
    float g = __expf(kf * (float)t0);
    float e = __expf(fmaf(lw, (float)t0, z0));  // may be inf -> w = 0 (correct)
    float xp = xrow[t0 ? t0 - 1 : 0];

    float p = 1.f, r = 0.f, q1 = 0.f, q2 = 0.f;
    float a1 = 0.f, a2 = 0.f, bt = 0.f, ws = 0.f;

    const float4* xv = (const float4*)(xrow + t0);
    float4 v = __ldcs(xv);
    const float y0 = __shfl_sync(FULLMASK, v.x, 0);

#define STEP(xval) do {                               \
    float w_ = __fdividef(1.f, 1.f + e);              \
    float f_ = fmaf(df, g, f_inf);                    \
    float i_ = __fdividef(1.f, cc + f_);              \
    float b_ = f_ * i_;                               \
    float ap = fmaf(-2.f, b_, 1.f);                   \
    g *= G; e *= R;                                   \
    float m_ = fmaf(b_, ap, b_);                      \
    float xx = (xval) + xp;                           \
    float u1 = b_ * xx;                               \
    float u2 = b_ * u1;                               \
    float pm = m_ * p;                                \
    float t2 = fmaf(m_, q1, u2);                      \
    p = ap * p;                                       \
    r = fmaf(ap, r, pm);                              \
    q1 = fmaf(ap, q1, u1);                            \
    q2 = fmaf(ap, q2, t2);                            \
    a1 = fmaf(w_, r, a1);                             \
    a2 = fmaf(w_, p, a2);                             \
    bt = fmaf(w_, q2, bt);                            \
    ws += w_;                                         \
    xp = (xval);                                      \
  } while (0)

    if (lane == 0) {
        // t = 0: y2_0 = y0 passes through identity -> a2 += w0, ws += w0
        float w0 = __fdividef(1.f, 1.f + e);
        a2 = w0; ws = w0;
        g *= G; e *= R;
        // xp stays X[0] for the t=1 step
    } else {
        STEP(v.x);
    }
    STEP(v.y); STEP(v.z); STEP(v.w);
    #pragma unroll 2
    for (int i = 1; i < 32; i++) {
        v = __ldcs(xv + i);
        STEP(v.x); STEP(v.y); STEP(v.z); STEP(v.w);
    }
#undef STEP

    // inclusive scan: compose self with prefix from lower lanes
    #pragma unroll
    for (int d = 1; d < 32; d <<= 1) {
        float pL  = __shfl_up_sync(FULLMASK, p,  d);
        float rL  = __shfl_up_sync(FULLMASK, r,  d);
        float q1L = __shfl_up_sync(FULLMASK, q1, d);
        float q2L = __shfl_up_sync(FULLMASK, q2, d);
        if (lane >= d) {
            float pn2 = p * pL;
            float rn  = fmaf(r, pL, p * rL);
            float q1n = fmaf(p, q1L, q1);
            float q2n = fmaf(r, q1L, fmaf(p, q2L, q2));
            p = pn2; r = rn; q1 = q1n; q2 = q2n;
        }
    }
    // exclusive shift (identity into lane 0)
    float pe  = __shfl_up_sync(FULLMASK, p,  1);
    float re  = __shfl_up_sync(FULLMASK, r,  1);
    float q1e = __shfl_up_sync(FULLMASK, q1, 1);
    float q2e = __shfl_up_sync(FULLMASK, q2, 1);
    if (lane == 0) { pe = 1.f; re = 0.f; q1e = 0.f; q2e = 0.f; }

    const float y1i = fmaf(pe, y0, q1e);
    const float y2i = fmaf(re + pe, y0, q2e);
    float contrib = fmaf(a1, y1i, fmaf(a2, y2i, bt));

    #pragma unroll
    for (int d = 16; d; d >>= 1) {
        contrib += __shfl_xor_sync(FULLMASK, contrib, d);
        ws      += __shfl_xor_sync(FULLMASK, ws, d);
    }
    if (lane == 0) out[row] = contrib / ws;
}

extern "C" void kernel_launch(void* const* d_in, const int* in_sizes, int n_in,
                              void* d_out, int out_size) {
    const float* X        = (const float*)d_in[0];
    const float* features = (const float*)d_in[1];
    const float* F        = (const float*)d_in[2];
    const float* bn0_g    = (const float*)d_in[3];
    const float* bn0_b    = (const float*)d_in[4];
    const float* W1       = (const float*)d_in[5];
    const float* b1       = (const float*)d_in[6];
    const float* bn1_g    = (const float*)d_in[7];
    const float* bn1_b    = (const float*)d_in[8];
    const float* W2       = (const float*)d_in[9];
    const float* b2       = (const float*)d_in[10];
    const float* bn2_g    = (const float*)d_in[11];
    const float* bn2_b    = (const float*)d_in[12];
    const float* W3       = (const float*)d_in[13];
    const float* b3       = (const float*)d_in[14];
    const float* pn       = (const float*)d_in[15];
    float* out = (float*)d_out;

    k_stats0<<<64, 256>>>(features);
    k_h1<<<16, 128>>>(features, bn0_g, bn0_b, W1, b1);
    k_h2<<<16, 128>>>(bn1_g, bn1_b, W2, b2);
    k_scan<<<256, 256>>>(X, F, bn2_g, bn2_b, W3, b3, pn, out);
}

// round 17
// speedup vs baseline: 1.0631x; 1.0631x over previous
#include <cuda_runtime.h>
#include <cuda_bf16.h>

#define FULLMASK 0xffffffffu
#define TT 4096

// ---- device scratch (allocation-free) ----
__device__ float g_s0part[8][64];    // feature col partial sum/sumsq per block
__device__ float g_a1part[16][16];   // h1 partial stats per block
__device__ float g_a2part[16][16];   // h2 partial stats per block
__device__ float g_h1[2048 * 8];
__device__ float g_h2[2048 * 8];
__device__ float g_params[2048 * 8]; // f_inf, df, kf, G, z0, lw, R, pad

__device__ __forceinline__ float rcpa(float x) {
    float r; asm("rcp.approx.f32 %0, %1;" : "=f"(r) : "f"(x)); return r;
}

// ============ K1: bn0 column stats over features [2048,32] ============
__global__ __launch_bounds__(256) void k1_stats0(const float* __restrict__ features) {
    __shared__ float red[8][64];
    int t = threadIdx.x, lane = t & 31, warp = t >> 5;
    int rbase = blockIdx.x * 256 + warp * 32 + (lane >> 3);
    int cg = (lane & 7) * 4;
    float s0=0,s1=0,s2=0,s3=0,q0=0,q1=0,q2=0,q3=0;
    #pragma unroll
    for (int i = 0; i < 8; i++) {
        float4 v = *(const float4*)(features + (size_t)(rbase + i * 4) * 32 + cg);
        s0 += v.x; s1 += v.y; s2 += v.z; s3 += v.w;
        q0 = fmaf(v.x, v.x, q0); q1 = fmaf(v.y, v.y, q1);
        q2 = fmaf(v.z, v.z, q2); q3 = fmaf(v.w, v.w, q3);
    }
    #pragma unroll
    for (int d = 8; d <= 16; d <<= 1) {
        s0 += __shfl_xor_sync(FULLMASK, s0, d); s1 += __shfl_xor_sync(FULLMASK, s1, d);
        s2 += __shfl_xor_sync(FULLMASK, s2, d); s3 += __shfl_xor_sync(FULLMASK, s3, d);
        q0 += __shfl_xor_sync(FULLMASK, q0, d); q1 += __shfl_xor_sync(FULLMASK, q1, d);
        q2 += __shfl_xor_sync(FULLMASK, q2, d); q3 += __shfl_xor_sync(FULLMASK, q3, d);
    }
    if (lane < 8) {
        red[warp][cg + 0] = s0; red[warp][cg + 1] = s1;
        red[warp][cg + 2] = s2; red[warp][cg + 3] = s3;
        red[warp][32 + cg + 0] = q0; red[warp][32 + cg + 1] = q1;
        red[warp][32 + cg + 2] = q2; red[warp][32 + cg + 3] = q3;
    }
    __syncthreads();
    if (t < 64) {
        float a = 0.f;
        #pragma unroll
        for (int w = 0; w < 8; w++) a += red[w][t];
        g_s0part[blockIdx.x][t] = a;
    }
}

// ============ K2: finalize bn0, h1 = bn0(features)@W1^T + b1, bn1 partials ============
__global__ __launch_bounds__(128) void k2_h1(const float* __restrict__ features,
                                             const float* __restrict__ bn0_g,
                                             const float* __restrict__ bn0_b,
                                             const float* __restrict__ W1,
                                             const float* __restrict__ b1) {
    __shared__ float sc0[32], sh0[32], sW[256], sb[8], wpart[4][16];
    int t = threadIdx.x;
    if (t < 32) {
        float ss = 0.f, qq = 0.f;
        #pragma unroll
        for (int k = 0; k < 8; k++) { ss += g_s0part[k][t]; qq += g_s0part[k][32 + t]; }
        float mean = ss * (1.f / 2048.f);
        float var = qq * (1.f / 2048.f) - mean * mean;
        float sc = bn0_g[t] * rsqrtf(var + 1e-5f);
        sc0[t] = sc; sh0[t] = bn0_b[t] - mean * sc;
    }
    sW[t] = W1[t]; sW[t + 128] = W1[t + 128];
    if (t < 8) sb[t] = b1[t];
    __syncthreads();

    int row = blockIdx.x * 128 + t;
    const float4* fp = (const float4*)(features + (size_t)row * 32);
    float x[32];
    #pragma unroll
    for (int i = 0; i < 8; i++) {
        float4 v = fp[i];
        x[4*i] = v.x; x[4*i+1] = v.y; x[4*i+2] = v.z; x[4*i+3] = v.w;
    }
    #pragma unroll
    for (int c = 0; c < 32; c++) x[c] = fmaf(x[c], sc0[c], sh0[c]);
    float h[8];
    #pragma unroll
    for (int j = 0; j < 8; j++) {
        float acc = sb[j];
        #pragma unroll
        for (int c = 0; c < 32; c++) acc = fmaf(sW[j * 32 + c], x[c], acc);
        h[j] = acc;
    }
    float4* hp = (float4*)(g_h1 + row * 8);
    hp[0] = make_float4(h[0], h[1], h[2], h[3]);
    hp[1] = make_float4(h[4], h[5], h[6], h[7]);

    float sv[16];
    #pragma unroll
    for (int j = 0; j < 8; j++) { sv[j] = h[j]; sv[8 + j] = h[j] * h[j]; }
    #pragma unroll
    for (int d = 16; d; d >>= 1) {
        #pragma unroll
        for (int j = 0; j < 16; j++) sv[j] += __shfl_xor_sync(FULLMASK, sv[j], d);
    }
    int warp = t >> 5, lane = t & 31;
    if (lane == 0) {
        #pragma unroll
        for (int j = 0; j < 16; j++) wpart[warp][j] = sv[j];
    }
    __syncthreads();
    if (t < 16)
        g_a1part[blockIdx.x][t] = wpart[0][t] + wpart[1][t] + wpart[2][t] + wpart[3][t];
}

// ============ K3: finalize bn1, h2 = relu(bn1(h1))@W2^T + b2, bn2 partials ============
__global__ __launch_bounds__(128) void k3_h2(const float* __restrict__ bn1_g,
                                             const float* __restrict__ bn1_b,
                                             const float* __restrict__ W2,
                                             const float* __restrict__ b2) {
    __shared__ float sc1[8], sh1[8], sW[64], sb[8], wpart[4][16];
    int t = threadIdx.x;
    if (t < 8) {
        float ss = 0.f, qq = 0.f;
        #pragma unroll
        for (int k = 0; k < 16; k++) { ss += g_a1part[k][t]; qq += g_a1part[k][8 + t]; }
        float mean = ss * (1.f / 2048.f);
        float var = qq * (1.f / 2048.f) - mean * mean;
        float sc = bn1_g[t] * rsqrtf(var + 1e-5f);
        sc1[t] = sc; sh1[t] = bn1_b[t] - mean * sc;
    }
    if (t < 64) sW[t] = W2[t];
    if (t < 8) sb[t] = b2[t];
    __syncthreads();

    int row = blockIdx.x * 128 + t;
    const float4* hp = (const float4*)(g_h1 + row * 8);
    float4 v0 = hp[0], v1 = hp[1];
    float z[8] = {v0.x, v0.y, v0.z, v0.w, v1.x, v1.y, v1.z, v1.w};
    #pragma unroll
    for (int j = 0; j < 8; j++) z[j] = fmaxf(fmaf(z[j], sc1[j], sh1[j]), 0.f);
    float h[8];
    #pragma unroll
    for (int k = 0; k < 8; k++) {
        float acc = sb[k];
        #pragma unroll
        for (int j = 0; j < 8; j++) acc = fmaf(sW[k * 8 + j], z[j], acc);
        h[k] = acc;
    }
    float4* op = (float4*)(g_h2 + row * 8);
    op[0] = make_float4(h[0], h[1], h[2], h[3]);
    op[1] = make_float4(h[4], h[5], h[6], h[7]);

    float sv[16];
    #pragma unroll
    for (int j = 0; j < 8; j++) { sv[j] = h[j]; sv[8 + j] = h[j] * h[j]; }
    #pragma unroll
    for (int d = 16; d; d >>= 1) {
        #pragma unroll
        for (int j = 0; j < 16; j++) sv[j] += __shfl_xor_sync(FULLMASK, sv[j], d);
    }
    int warp = t >> 5, lane = t & 31;
    if (lane == 0) {
        #pragma unroll
        for (int j = 0; j < 16; j++) wpart[warp][j] = sv[j];
    }
    __syncthreads();
    if (t < 16)
        g_a2part[blockIdx.x][t] = wpart[0][t] + wpart[1][t] + wpart[2][t] + wpart[3][t];
}

// ============ K4: finalize bn2, corr -> sigmoid -> per-row scan params ============
__global__ __launch_bounds__(128) void k4_params(const float* __restrict__ bn2_g,
                                                 const float* __restrict__ bn2_b,
                                                 const float* __restrict__ W3,
                                                 const float* __restrict__ b3,
                                                 const float* __restrict__ pn) {
    __shared__ float sc2[8], sh2[8], sW[48], sb[6], spn[6];
    int t = threadIdx.x;
    if (t < 8) {
        float ss = 0.f, qq = 0.f;
        #pragma unroll
        for (int k = 0; k < 16; k++) { ss += g_a2part[k][t]; qq += g_a2part[k][8 + t]; }
        float mean = ss * (1.f / 2048.f);
        float var = qq * (1.f / 2048.f) - mean * mean;
        float sc = bn2_g[t] * rsqrtf(var + 1e-5f);
        sc2[t] = sc; sh2[t] = bn2_b[t] - mean * sc;
    }
    if (t < 48) sW[t] = W3[t];
    if (t < 6) { sb[t] = b3[t]; spn[t] = pn[t]; }
    __syncthreads();

    int row = blockIdx.x * 128 + t;
    const float4* hp = (const float4*)(g_h2 + row * 8);
    float4 v0 = hp[0], v1 = hp[1];
    float z[8] = {v0.x, v0.y, v0.z, v0.w, v1.x, v1.y, v1.z, v1.w};
    #pragma unroll
    for (int j = 0; j < 8; j++) z[j] = fmaxf(fmaf(z[j], sc2[j], sh2[j]), 0.f);
    float sg[6];
    #pragma unroll
    for (int j = 0; j < 6; j++) {
        float acc = sb[j] + spn[j];
        #pragma unroll
        for (int k = 0; k < 8; k++) acc = fmaf(sW[j * 8 + k], z[k], acc);
        sg[j] = 1.f / (1.f + expf(-acc));
    }
    float f_start = fmaf(4.5f, sg[0], 0.5f);
    float f_inf   = fmaf(0.49f, sg[1], 0.01f);
    float f_decay = 2.f * sg[2];
    float f_T     = 2.f * sg[3];
    float w_off   = sg[4];
    float w_T     = fmaf(0.49f, sg[5], 0.01f);

    float df  = f_start - f_inf;
    float lnD = fmaf(-2.30258509f, f_decay, -0.35667494f);  // ln(0.7*0.1^fd)
    float H   = 10.f * expf(-2.30258509f * f_T);            // 10*0.1^fT
    float kf  = lnD / (4096.f * H);
    float G   = expf(kf);
    float z0  = w_off / w_T;
    float lw  = -1.f / (4096.f * w_T);
    float R   = expf(lw);

    float4* op = (float4*)(g_params + row * 8);
    op[0] = make_float4(f_inf, df, kf, G);
    op[1] = make_float4(z0, lw, R, 0.f);
}

// ============ K5: affine-chunked IIR scan + weighted average (256 x 256) ============
// Lane l scans steps [128l, 128l+128) in closed affine form. Coefficient
// recurrences track the SHIFTED quantities: ee = 1+e (w = rcp(ee)) and
// cf = cc+f (b = 1 - cc*rcp(cf)), each advanced by a single fma — saving
// 2 fma-pipe ops per step vs the explicit g/e form. Exact re-init per chunk.
__global__ __launch_bounds__(256) void k5_scan(const float* __restrict__ X,
                                               const float* __restrict__ Fp,
                                               float* __restrict__ out) {
    int warp = threadIdx.x >> 5, lane = threadIdx.x & 31;
    int row = blockIdx.x * 8 + warp;
    const float cc = 0.16228221f * __ldg(Fp);   // sqrt(2^(1/3)-1)*F/pi

    const float4 c0 = *(const float4*)(g_params + row * 8);
    const float4 c1 = *(const float4*)(g_params + row * 8 + 4);
    const float f_inf = c0.x, df = c0.y, kf = c0.z, G = c0.w;
    const float z0 = c1.x, lw = c1.y, R = c1.z;

    const float Kcf = (cc + f_inf) * (1.f - G);
    const float Ke  = 1.f - R;

    const float* xrow = X + (size_t)row * TT;
    const int t0 = lane << 7;
    const float t0f = (float)t0;
    float cf = cc + fmaf(df, __expf(kf * t0f), f_inf);
    float ee = 1.f + __expf(fmaf(lw, t0f, z0));   // may be inf -> w = 0 (correct)
    float xp = xrow[t0 ? t0 - 1 : 0];

    float p = 1.f, r = 0.f, q1 = 0.f, q2 = 0.f;
    float a1 = 0.f, a2 = 0.f, bt = 0.f, ws = 0.f;

    const float4* xv = (const float4*)(xrow + t0);
    float4 v = __ldcs(xv);
    const float y0 = __shfl_sync(FULLMASK, v.x, 0);

#define STEP(xval) do {                               \
    float w_ = rcpa(ee);                              \
    float i_ = rcpa(cf);                              \
    float b_ = fmaf(-cc, i_, 1.f);                    \
    float ap = fmaf(-2.f, b_, 1.f);                   \
    ee = fmaf(R, ee, Ke);                             \
    cf = fmaf(G, cf, Kcf);                            \
    float m_ = fmaf(b_, ap, b_);                      \
    float xx = (xval) + xp;                           \
    float u1 = b_ * xx;                               \
    float u2 = b_ * u1;                               \
    float pm = m_ * p;                                \
    float t2 = fmaf(m_, q1, u2);                      \
    p = ap * p;                                       \
    r = fmaf(ap, r, pm);                              \
    q1 = fmaf(ap, q1, u1);                            \
    q2 = fmaf(ap, q2, t2);                            \
    a1 = fmaf(w_, r, a1);                             \
    a2 = fmaf(w_, p, a2);                             \
    bt = fmaf(w_, q2, bt);                            \
    ws += w_;                                         \
    xp = (xval);                                      \
  } while (0)

    if (lane == 0) {
        // t = 0: y2_0 = y0 passes through identity -> a2 += w0, ws += w0
        float w0 = rcpa(ee);
        a2 = w0; ws = w0;
        ee = fmaf(R, ee, Ke);
        cf = fmaf(G, cf, Kcf);
        // xp stays X[0] for the t=1 step
    } else {
        STEP(v.x);
    }
    STEP(v.y); STEP(v.z); STEP(v.w);
    #pragma unroll 2
    for (int i = 1; i < 32; i++) {
        v = __ldcs(xv + i);
        STEP(v.x); STEP(v.y); STEP(v.z); STEP(v.w);
    }
#undef STEP

    // inclusive scan: compose self with prefix from lower lanes
    #pragma unroll
    for (int d = 1; d < 32; d <<= 1) {
        float pL  = __shfl_up_sync(FULLMASK, p,  d);
        float rL  = __shfl_up_sync(FULLMASK, r,  d);
        float q1L = __shfl_up_sync(FULLMASK, q1, d);
        float q2L = __shfl_up_sync(FULLMASK, q2, d);
        if (lane >= d) {
            float pn2 = p * pL;
            float rn  = fmaf(r, pL, p * rL);
            float q1n = fmaf(p, q1L, q1);
            float q2n = fmaf(r, q1L, fmaf(p, q2L, q2));
            p = pn2; r = rn; q1 = q1n; q2 = q2n;
        }
    }
    // exclusive shift (identity into lane 0)
    float pe  = __shfl_up_sync(FULLMASK, p,  1);
    float re  = __shfl_up_sync(FULLMASK, r,  1);
    float q1e = __shfl_up_sync(FULLMASK, q1, 1);
    float q2e = __shfl_up_sync(FULLMASK, q2, 1);
    if (lane == 0) { pe = 1.f; re = 0.f; q1e = 0.f; q2e = 0.f; }

    const float y1i = fmaf(pe, y0, q1e);
    const float y2i = fmaf(re + pe, y0, q2e);
    float contrib = fmaf(a1, y1i, fmaf(a2, y2i, bt));

    #pragma unroll
    for (int d = 16; d; d >>= 1) {
        contrib += __shfl_xor_sync(FULLMASK, contrib, d);
        ws      += __shfl_xor_sync(FULLMASK, ws, d);
    }
    if (lane == 0) out[row] = contrib / ws;
}

extern "C" void kernel_launch(void* const* d_in, const int* in_sizes, int n_in,
                              void* d_out, int out_size) {
    const float* X        = (const float*)d_in[0];
    const float* features = (const float*)d_in[1];
    const float* F        = (const float*)d_in[2];
    const float* bn0_g    = (const float*)d_in[3];
    const float* bn0_b    = (const float*)d_in[4];
    const float* W1       = (const float*)d_in[5];
    const float* b1       = (const float*)d_in[6];
    const float* bn1_g    = (const float*)d_in[7];
    const float* bn1_b    = (const float*)d_in[8];
    const float* W2       = (const float*)d_in[9];
    const float* b2       = (const float*)d_in[10];
    const float* bn2_g    = (const float*)d_in[11];
    const float* bn2_b    = (const float*)d_in[12];
    const float* W3       = (const float*)d_in[13];
    const float* b3       = (const float*)d_in[14];
    const float* pn       = (const float*)d_in[15];
    float* out = (float*)d_out;

    k1_stats0<<<8, 256>>>(features);
    k2_h1<<<16, 128>>>(features, bn0_g, bn0_b, W1, b1);
    k3_h2<<<16, 128>>>(bn1_g, bn1_b, W2, b2);
    k4_params<<<16, 128>>>(bn2_g, bn2_b, W3, b3, pn);
    k5_scan<<<256, 256>>>(X, F, out);
}